// round 8
// baseline (speedup 1.0000x reference)
#include <cuda_runtime.h>
#include <math.h>
#include <stdint.h>

// Problem constants
#define BATCH 128
#define T_ENC 1024
#define T_DEC 250
#define GS 16          // blocks per group
#define NGROUP 8
// Output layout: seq2seq (128,1250,80) | alphas (250,128,1024) | weight_pers (250)
#define SEQ_STRIDE_B 100000
#define ALPHA_OFF   12800000ll
#define WPER_OFF    45568000ll

// ---------------- device scratch ----------------
__device__ float g_keys[BATCH * T_ENC * 256];     // enc @ Wk + bk (134 MB)
__device__ float g_ss  [BATCH * 256];
__device__ float g_hatt[BATCH * 256];
__device__ float g_h1  [BATCH * 256];
__device__ float g_h2  [BATCH * 256];
__device__ float g_ctx [BATCH * 256];
__device__ float g_p   [BATCH * 128];
__device__ float g_rh  [BATCH * 256];
__device__ float g_u   [BATCH * 256];
__device__ float g_din [BATCH * 256];
__device__ float g_o1  [BATCH * 256];
__device__ float g_o2  [BATCH * 256];
__device__ float g_wpart[T_DEC * BATCH];
__device__ unsigned g_barctr[NGROUP * 32];        // one ctr per group, 128B apart

// ---------------- math helpers ----------------
__device__ __forceinline__ float fsig(float x) {
    return __fdividef(1.0f, 1.0f + __expf(-x));
}
__device__ __forceinline__ float ftanh(float x) {       // accurate (GRU recurrence)
    float xx = fminf(fmaxf(x, -15.0f), 15.0f);
    float e  = __expf(2.0f * xx);
    return __fdividef(e - 1.0f, e + 1.0f);
}
__device__ __forceinline__ float tanhap(float x) {      // HW tanh (energies only)
    float y;
    asm("tanh.approx.f32 %0, %1;" : "=f"(y) : "f"(x));
    return y;
}

// ---------------- group barrier (monotonic, counters reset by init each replay) --
__device__ __forceinline__ void gbar(unsigned* ctr, unsigned& tgt) {
    __syncthreads();
    tgt += GS;
    if (threadIdx.x == 0) {
        __threadfence();
        atomicAdd(ctr, 1u);
        while (*((volatile unsigned*)ctr) < tgt) { __nanosleep(16); }
        __threadfence();
    }
    __syncthreads();
}

// =============================================================================
// keys = enc @ Wk + bk.  M=131072, K=256, N=256. (verified correct in R5)
// =============================================================================
__global__ void keys_gemm(const float* __restrict__ A, const float* __restrict__ Wk,
                          const float* __restrict__ bk, float* __restrict__ out) {
    __shared__ float As[16][68];
    __shared__ float Bs[16][68];
    const int tid  = threadIdx.x;
    const int trow = tid >> 4, tcol = tid & 15;
    const int row0 = blockIdx.y * 64, col0 = blockIdx.x * 64;
    float c[4][4];
#pragma unroll
    for (int i = 0; i < 4; i++)
#pragma unroll
        for (int j = 0; j < 4; j++) c[i][j] = 0.0f;
    const int ar = tid >> 2, ak = (tid & 3) * 4;
    const int bkr = tid >> 4, bn = (tid & 15) * 4;
    for (int k0 = 0; k0 < 256; k0 += 16) {
        float4 a4 = *(const float4*)(A + (size_t)(row0 + ar) * 256 + k0 + ak);
        As[ak + 0][ar] = a4.x; As[ak + 1][ar] = a4.y;
        As[ak + 2][ar] = a4.z; As[ak + 3][ar] = a4.w;
        float4 b4 = *(const float4*)(Wk + (size_t)(k0 + bkr) * 256 + col0 + bn);
        *(float4*)&Bs[bkr][bn] = b4;
        __syncthreads();
#pragma unroll
        for (int kk = 0; kk < 16; kk++) {
            float4 a = *(float4*)&As[kk][trow * 4];
            float4 b = *(float4*)&Bs[kk][tcol * 4];
            c[0][0] += a.x * b.x; c[0][1] += a.x * b.y; c[0][2] += a.x * b.z; c[0][3] += a.x * b.w;
            c[1][0] += a.y * b.x; c[1][1] += a.y * b.y; c[1][2] += a.y * b.z; c[1][3] += a.y * b.w;
            c[2][0] += a.z * b.x; c[2][1] += a.z * b.y; c[2][2] += a.z * b.z; c[2][3] += a.z * b.w;
            c[3][0] += a.w * b.x; c[3][1] += a.w * b.y; c[3][2] += a.w * b.z; c[3][3] += a.w * b.w;
        }
        __syncthreads();
    }
#pragma unroll
    for (int i = 0; i < 4; i++) {
        size_t r = (size_t)(row0 + trow * 4 + i) * 256;
#pragma unroll
        for (int j = 0; j < 4; j++) {
            int cc = col0 + tcol * 4 + j;
            out[r + cc] = c[i][j] + bk[cc];
        }
    }
}

// =============================================================================
// init: sentence_style, zero state, reset group barriers. Runs every replay.
// =============================================================================
__global__ void init_kernel(const float* __restrict__ inp_att,
                            const float* __restrict__ style_token) {
    int b = blockIdx.x, d = threadIdx.x;      // 128 x 256
    float s = 0.0f;
#pragma unroll
    for (int k = 0; k < 10; k++) s += inp_att[b * 10 + k] * style_token[k * 256 + d];
    int idx = b * 256 + d;
    g_ss[idx]   = s;
    g_hatt[idx] = 0.0f; g_h1[idx] = 0.0f; g_h2[idx] = 0.0f; g_ctx[idx] = 0.0f;
    if (b == 0 && d < NGROUP * 32) g_barctr[d] = 0u;
}

// ---------------- column-phase helpers (group of 16 blocks, 16 rows) ----------
struct Seg3 { const float* a; const float* bp; const float* c; };

template<int LA, int LB>
__device__ __forceinline__ float segld(const Seg3& s, int row, int k) {
    if (LA && k < LA) return __ldcg(s.a + row * LA + k);
    if (LB && k - LA < LB) return __ldcg(s.bp + row * LB + (k - LA));
    return __ldcg(s.c + row * 256 + (k - LA - LB));
}

template<int K, int LA, int LB>
__device__ __forceinline__ void stageX(float* Xs, Seg3 s, int R0, int tid) {
    constexpr int total = 16 * K;
#pragma unroll
    for (int i0 = 0; i0 < total; i0 += 1024) {
        int i = i0 + tid;
        int r = i / K, k = i - r * K;
        Xs[i] = segld<LA, LB>(s, R0 + r, k);
    }
    __syncthreads();
}

// gates: N=512 (32 cols/block), sigmoid -> rh (cols<256, = g*h) and u.
template<int K>
__device__ __forceinline__ void col_gates(const float* Xs, const float* __restrict__ W,
                                          const float* __restrict__ bg,
                                          const float* h, int R0, int sub, int tid) {
    const int o = tid >> 1, half = tid & 1;
    const int r = o >> 5, cl = o & 31, col = sub * 32 + cl;
    constexpr int Kh = K >> 1;
    const int k0 = half * Kh;
    const float* Xp = Xs + r * K + k0;
    const float* Wp = W + (size_t)k0 * 512 + col;
    float acc = 0.0f;
#pragma unroll 16
    for (int k = 0; k < Kh; k++) acc += Xp[k] * Wp[(size_t)k * 512];
    acc += __shfl_xor_sync(0xffffffffu, acc, 1);
    if (half == 0) {
        const int row = R0 + r;
        float y = fsig(acc + bg[col]);
        if (col < 256) g_rh[row * 256 + col] = y * __ldcg(h + row * 256 + col);
        else           g_u[row * 256 + col - 256] = y;
    }
}

// candidate: N=256 (16 cols/block), tanh -> h' = u*h+(1-u)*c; optional o = h'+xadd.
template<int K>
__device__ __forceinline__ void col_cand(const float* Xs, const float* __restrict__ W,
                                         const float* __restrict__ bc,
                                         float* h, float* o_out, const float* xadd,
                                         int R0, int sub, int tid) {
    const int o = tid >> 2, q4 = tid & 3;
    const int r = o >> 4, cl = o & 15, col = sub * 16 + cl;
    constexpr int Kq = K >> 2;
    const int k0 = q4 * Kq;
    const float* Xp = Xs + r * K + k0;
    const float* Wp = W + (size_t)k0 * 256 + col;
    float acc = 0.0f;
#pragma unroll 16
    for (int k = 0; k < Kq; k++) acc += Xp[k] * Wp[(size_t)k * 256];
    acc += __shfl_xor_sync(0xffffffffu, acc, 1);
    acc += __shfl_xor_sync(0xffffffffu, acc, 2);
    if (q4 == 0) {
        const int row = R0 + r;
        float c  = ftanh(acc + bc[col]);
        float un = __ldcg(g_u + row * 256 + col);
        float ho = __ldcg(h + row * 256 + col);
        float hn = un * ho + (1.0f - un) * c;
        h[row * 256 + col] = hn;
        if (o_out) o_out[row * 256 + col] = hn + __ldcg(xadd + row * 256 + col);
    }
}

// =============================================================================
// Persistent scan kernel: 128 blocks x 1024 threads, whole 250-step recurrence.
// =============================================================================
__global__ void __launch_bounds__(1024, 1)
scan_kernel(const float* __restrict__ enc, const int* __restrict__ mask,
            const float* __restrict__ vvec,
            const float* __restrict__ pre_W1, const float* __restrict__ pre_b1,
            const float* __restrict__ pre_W2, const float* __restrict__ pre_b2,
            const float* __restrict__ att_Wg, const float* __restrict__ att_bg,
            const float* __restrict__ att_Wc, const float* __restrict__ att_bc,
            const float* __restrict__ attn_Wq, const float* __restrict__ attn_bq,
            const float* __restrict__ deciW, const float* __restrict__ decib,
            const float* __restrict__ d1Wg, const float* __restrict__ d1bg,
            const float* __restrict__ d1Wc, const float* __restrict__ d1bc,
            const float* __restrict__ d2Wg, const float* __restrict__ d2bg,
            const float* __restrict__ d2Wc, const float* __restrict__ d2bc,
            const float* __restrict__ outW, const float* __restrict__ outb,
            float* __restrict__ dout) {
    __shared__ float sm[10240];                  // X staging / es+red alias (40 KB)
    __shared__ float qs[256], vs[256], hs[256], sss[256], cs[256];
    const int b = blockIdx.x, tid = threadIdx.x;
    const int g = b >> 4, sub = b & 15, R0 = g * 16;
    unsigned* ctr = &g_barctr[g * 32];
    unsigned tgt = 0;

    if (tid < 256) { vs[tid] = vvec[tid]; sss[tid] = g_ss[b * 256 + tid]; }
    const int ml = mask[b];
    const int wid = tid >> 5, lane = tid & 31;
    float* es  = sm;
    float* red = sm + 1024;

    for (int t = 0; t < T_DEC; t++) {
        // ---------- Phase 1 (row): prenet -> g_p[b] ----------
        if (tid < 80)
            sm[tid] = (t == 0) ? 0.0f
                     : __ldcg(dout + (size_t)b * SEQ_STRIDE_B + (size_t)(t - 1) * 400 + 320 + tid);
        __syncthreads();
        {   // L1: 80 -> 256 relu (4 threads/col)
            const int col = tid >> 2, part = tid & 3;
            float acc = 0.0f;
#pragma unroll
            for (int k = 0; k < 20; k++) acc += sm[part * 20 + k] * pre_W1[(size_t)(part * 20 + k) * 256 + col];
            acc += __shfl_xor_sync(0xffffffffu, acc, 1);
            acc += __shfl_xor_sync(0xffffffffu, acc, 2);
            __syncthreads();
            if (part == 0) sm[128 + col] = fmaxf(acc + pre_b1[col], 0.0f);
        }
        __syncthreads();
        {   // L2: 256 -> 128 relu (8 threads/col)
            const int col = tid >> 3, part = tid & 7;
            float acc = 0.0f;
#pragma unroll 8
            for (int k = 0; k < 32; k++) acc += sm[128 + part * 32 + k] * pre_W2[(size_t)(part * 32 + k) * 128 + col];
            acc += __shfl_xor_sync(0xffffffffu, acc, 1);
            acc += __shfl_xor_sync(0xffffffffu, acc, 2);
            acc += __shfl_xor_sync(0xffffffffu, acc, 4);
            if (part == 0) g_p[b * 128 + col] = fmaxf(acc + pre_b2[col], 0.0f);
        }
        gbar(ctr, tgt);

        // ---------- Phase 2 (col): att GRU gates, K=640, X=[ctx,p,hatt] ----------
        stageX<640, 256, 128>(sm, Seg3{g_ctx, g_p, g_hatt}, R0, tid);
        col_gates<640>(sm, att_Wg, att_bg, g_hatt, R0, sub, tid);
        gbar(ctr, tgt);

        // ---------- Phase 3 (col): att GRU cand, K=640, X=[ctx,p,rh] -> hatt ----------
        stageX<640, 256, 128>(sm, Seg3{g_ctx, g_p, g_rh}, R0, tid);
        col_cand<640>(sm, att_Wc, att_bc, g_hatt, nullptr, nullptr, R0, sub, tid);
        gbar(ctr, tgt);

        // ---------- Phase 4 (row): q, energies, softmax, context, wper, dec_in ----------
        if (tid < 256) hs[tid] = __ldcg(g_hatt + b * 256 + tid);
        __syncthreads();
        {   // q = hs @ Wq + bq (4 threads/col)
            const int col = tid >> 2, part = tid & 3;
            float acc = 0.0f;
#pragma unroll 8
            for (int k = 0; k < 64; k++) acc += hs[part * 64 + k] * attn_Wq[(size_t)(part * 64 + k) * 256 + col];
            acc += __shfl_xor_sync(0xffffffffu, acc, 1);
            acc += __shfl_xor_sync(0xffffffffu, acc, 2);
            if (part == 0) qs[col] = acc + attn_bq[col];
        }
        __syncthreads();
        {   // energies: 32 warps x 32 rows
            float vf[8], qf[8];
#pragma unroll
            for (int j = 0; j < 8; j++) { vf[j] = vs[lane + 32 * j]; qf[j] = qs[lane + 32 * j]; }
            const float* kb2 = g_keys + (size_t)b * T_ENC * 256;
            for (int tt = wid; tt < 1024; tt += 32) {
                const float* kp = kb2 + (size_t)tt * 256;
                float acc = 0.0f;
#pragma unroll
                for (int j = 0; j < 8; j++) {
                    float x = __ldcs(kp + lane + 32 * j) + qf[j];
                    acc += tanhap(x) * vf[j];
                }
#pragma unroll
                for (int o = 16; o; o >>= 1) acc += __shfl_xor_sync(0xffffffffu, acc, o);
                if (lane == 0) es[tt] = (tt < ml) ? acc : -1.0e9f;
            }
        }
        __syncthreads();
        // softmax over 1024
        red[tid] = es[tid]; __syncthreads();
        for (int s = 512; s; s >>= 1) { if (tid < s) red[tid] = fmaxf(red[tid], red[tid + s]); __syncthreads(); }
        float mx = red[0];
        __syncthreads();
        float e0 = __expf(es[tid] - mx);
        red[tid] = e0; __syncthreads();
        for (int s = 512; s; s >>= 1) { if (tid < s) red[tid] += red[tid + s]; __syncthreads(); }
        float inv = 1.0f / red[0];
        __syncthreads();
        float a0 = e0 * inv;
        es[tid] = a0;
        dout[ALPHA_OFF + ((size_t)t * BATCH + b) * 1024 + tid] = a0;
        __syncthreads();
        {   // context + wper
            const int gq = tid >> 8, d = tid & 255;
            const float* eb = enc + (size_t)b * T_ENC * 256;
            const int tbase = gq * 256;
            float acc = 0.0f;
            for (int tt = 0; tt < 256; tt += 4) {
#pragma unroll
                for (int u2 = 0; u2 < 4; u2++)
                    acc += es[tbase + tt + u2] * __ldcs(eb + (size_t)(tbase + tt + u2) * 256 + d);
            }
            red[tid] = acc; __syncthreads();
            float f = 0.0f;
            if (tid < 256) {
                float c = red[tid] + red[tid + 256] + red[tid + 512] + red[tid + 768];
                cs[tid] = c;
                g_ctx[b * 256 + tid] = c;
                float as = fabsf(sss[tid]);
                f = __fdividef(as, fabsf(c) + as);
            }
            __syncthreads();
            red[tid] = f; __syncthreads();
            for (int s = 512; s; s >>= 1) { if (tid < s) red[tid] += red[tid + s]; __syncthreads(); }
            if (tid == 0) g_wpart[t * BATCH + b] = red[0];
            __syncthreads();
        }
        {   // dec_in = [hs, cs+sss] @ deciW + decib (4 threads/col)
            const int col = tid >> 2, part = tid & 3;
            const int kb3 = part * 128;
            float acc = 0.0f;
#pragma unroll 16
            for (int k = 0; k < 128; k++) {
                int kk = kb3 + k;
                float x = (kk < 256) ? hs[kk] : (cs[kk - 256] + sss[kk - 256]);
                acc += x * deciW[(size_t)kk * 256 + col];
            }
            acc += __shfl_xor_sync(0xffffffffu, acc, 1);
            acc += __shfl_xor_sync(0xffffffffu, acc, 2);
            if (part == 0) g_din[b * 256 + col] = acc + decib[col];
        }
        gbar(ctr, tgt);

        // ---------- Phase 5/6: dec1 GRU ----------
        stageX<512, 256, 256>(sm, Seg3{g_din, g_h1, nullptr}, R0, tid);
        col_gates<512>(sm, d1Wg, d1bg, g_h1, R0, sub, tid);
        gbar(ctr, tgt);
        stageX<512, 256, 256>(sm, Seg3{g_din, g_rh, nullptr}, R0, tid);
        col_cand<512>(sm, d1Wc, d1bc, g_h1, g_o1, g_din, R0, sub, tid);
        gbar(ctr, tgt);

        // ---------- Phase 7/8: dec2 GRU ----------
        stageX<512, 256, 256>(sm, Seg3{g_o1, g_h2, nullptr}, R0, tid);
        col_gates<512>(sm, d2Wg, d2bg, g_h2, R0, sub, tid);
        gbar(ctr, tgt);
        stageX<512, 256, 256>(sm, Seg3{g_o1, g_rh, nullptr}, R0, tid);
        col_cand<512>(sm, d2Wc, d2bc, g_h2, g_o2, g_o1, R0, sub, tid);
        gbar(ctr, tgt);

        // ---------- Phase 9 (col): dense_out = o2 @ outW + outb -> slab ----------
        if (sub < 13) {
            stageX<256, 256, 0>(sm, Seg3{g_o2, nullptr, nullptr}, R0, tid);
            const int o = tid >> 1, half = tid & 1;
            const int r = o >> 5, cl = o & 31, col = sub * 32 + cl;
            const int colc = (col < 400) ? col : 399;
            const float* Xp = sm + r * 256 + half * 128;
            const float* Wp = outW + (size_t)(half * 128) * 400 + colc;
            float acc = 0.0f;
#pragma unroll 16
            for (int k = 0; k < 128; k++) acc += Xp[k] * Wp[(size_t)k * 400];
            acc += __shfl_xor_sync(0xffffffffu, acc, 1);
            if (half == 0 && col < 400) {
                const int row = R0 + r;
                dout[(size_t)row * SEQ_STRIDE_B + (size_t)t * 400 + col] = acc + outb[col];
            }
        }
        gbar(ctr, tgt);
    }
}

// =============================================================================
// Finalize weight_pers: deterministic reduction of 128 partials per step.
// =============================================================================
__global__ void final_kernel(float* __restrict__ dout) {
    __shared__ float red[128];
    const int t = blockIdx.x, tid = threadIdx.x;   // 250 x 128
    red[tid] = g_wpart[t * BATCH + tid];
    __syncthreads();
    for (int s = 64; s; s >>= 1) { if (tid < s) red[tid] += red[tid + s]; __syncthreads(); }
    if (tid == 0) dout[WPER_OFF + t] = red[0] * (1.0f / 32768.0f);
}

// =============================================================================
// Host
// =============================================================================
extern "C" void kernel_launch(void* const* d_in, const int* in_sizes, int n_in,
                              void* d_out, int out_size) {
    const float* enc         = (const float*)d_in[0];
    const int*   inp_mask    = (const int*)  d_in[1];
    const float* inp_att     = (const float*)d_in[2];
    const float* style_token = (const float*)d_in[3];
    const float* pre_W1 = (const float*)d_in[4];
    const float* pre_b1 = (const float*)d_in[5];
    const float* pre_W2 = (const float*)d_in[6];
    const float* pre_b2 = (const float*)d_in[7];
    const float* att_Wg = (const float*)d_in[8];
    const float* att_bg = (const float*)d_in[9];
    const float* att_Wc = (const float*)d_in[10];
    const float* att_bc = (const float*)d_in[11];
    const float* attn_Wk = (const float*)d_in[12];
    const float* attn_bk = (const float*)d_in[13];
    const float* attn_Wq = (const float*)d_in[14];
    const float* attn_bq = (const float*)d_in[15];
    const float* attn_v  = (const float*)d_in[16];
    const float* deci_W  = (const float*)d_in[17];
    const float* deci_b  = (const float*)d_in[18];
    const float* dec1_Wg = (const float*)d_in[19];
    const float* dec1_bg = (const float*)d_in[20];
    const float* dec1_Wc = (const float*)d_in[21];
    const float* dec1_bc = (const float*)d_in[22];
    const float* dec2_Wg = (const float*)d_in[23];
    const float* dec2_bg = (const float*)d_in[24];
    const float* dec2_Wc = (const float*)d_in[25];
    const float* dec2_bc = (const float*)d_in[26];
    const float* out_W   = (const float*)d_in[27];
    const float* out_b   = (const float*)d_in[28];
    float* dout = (float*)d_out;

    float* keys;
    cudaGetSymbolAddress((void**)&keys, g_keys);

    keys_gemm<<<dim3(4, (BATCH * T_ENC) / 64), 256>>>(enc, attn_Wk, attn_bk, keys);
    init_kernel<<<BATCH, 256>>>(inp_att, style_token);
    scan_kernel<<<BATCH, 1024>>>(enc, inp_mask, attn_v,
                                 pre_W1, pre_b1, pre_W2, pre_b2,
                                 att_Wg, att_bg, att_Wc, att_bc,
                                 attn_Wq, attn_bq, deci_W, deci_b,
                                 dec1_Wg, dec1_bg, dec1_Wc, dec1_bc,
                                 dec2_Wg, dec2_bg, dec2_Wc, dec2_bc,
                                 out_W, out_b, dout);
    final_kernel<<<T_DEC, 128>>>(dout);
}

// round 9
// speedup vs baseline: 1.5400x; 1.5400x over previous
#include <cuda_runtime.h>
#include <math.h>
#include <stdint.h>

// Problem constants
#define BATCH 128
#define T_ENC 1024
#define T_DEC 250
#define GS 16          // blocks per group
#define NGROUP 8
// Output layout: seq2seq (128,1250,80) | alphas (250,128,1024) | weight_pers (250)
#define SEQ_STRIDE_B 100000
#define ALPHA_OFF   12800000ll
#define WPER_OFF    45568000ll

// ---------------- device scratch ----------------
__device__ float g_keys[BATCH * T_ENC * 256];     // enc @ Wk + bk (134 MB)
__device__ float g_ss  [BATCH * 256];
__device__ float g_hatt[BATCH * 256];
__device__ float g_h1  [BATCH * 256];
__device__ float g_h2  [BATCH * 256];
__device__ float g_ctx [BATCH * 256];
__device__ float g_p   [BATCH * 128];
__device__ float g_rh  [BATCH * 256];
__device__ float g_u   [BATCH * 256];
__device__ float g_din [BATCH * 256];
__device__ float g_o1  [BATCH * 256];
__device__ float g_o2  [BATCH * 256];
__device__ float g_wpart[T_DEC * BATCH];
__device__ unsigned g_barctr[NGROUP * 32];        // one ctr per group, 128B apart

// ---------------- math helpers ----------------
__device__ __forceinline__ float fsig(float x) {
    return __fdividef(1.0f, 1.0f + __expf(-x));
}
__device__ __forceinline__ float ftanh(float x) {       // accurate (GRU recurrence)
    float xx = fminf(fmaxf(x, -15.0f), 15.0f);
    float e  = __expf(2.0f * xx);
    return __fdividef(e - 1.0f, e + 1.0f);
}
__device__ __forceinline__ float tanhap(float x) {      // HW tanh (energies only)
    float y;
    asm("tanh.approx.f32 %0, %1;" : "=f"(y) : "f"(x));
    return y;
}

// ---------------- group barrier (monotonic; counters reset by init each replay) --
__device__ __forceinline__ void gbar(unsigned* ctr, unsigned& tgt) {
    __syncthreads();
    tgt += GS;
    if (threadIdx.x == 0) {
        __threadfence();
        atomicAdd(ctr, 1u);
        while (*((volatile unsigned*)ctr) < tgt) { __nanosleep(16); }
        __threadfence();
    }
    __syncthreads();
}

// =============================================================================
// keys = enc @ Wk + bk.  M=131072, K=256, N=256. (verified correct in R8)
// =============================================================================
__global__ void keys_gemm(const float* __restrict__ A, const float* __restrict__ Wk,
                          const float* __restrict__ bk, float* __restrict__ out) {
    __shared__ float As[16][68];
    __shared__ float Bs[16][68];
    const int tid  = threadIdx.x;
    const int trow = tid >> 4, tcol = tid & 15;
    const int row0 = blockIdx.y * 64, col0 = blockIdx.x * 64;
    float c[4][4];
#pragma unroll
    for (int i = 0; i < 4; i++)
#pragma unroll
        for (int j = 0; j < 4; j++) c[i][j] = 0.0f;
    const int ar = tid >> 2, ak = (tid & 3) * 4;
    const int bkr = tid >> 4, bn = (tid & 15) * 4;
    for (int k0 = 0; k0 < 256; k0 += 16) {
        float4 a4 = *(const float4*)(A + (size_t)(row0 + ar) * 256 + k0 + ak);
        As[ak + 0][ar] = a4.x; As[ak + 1][ar] = a4.y;
        As[ak + 2][ar] = a4.z; As[ak + 3][ar] = a4.w;
        float4 b4 = *(const float4*)(Wk + (size_t)(k0 + bkr) * 256 + col0 + bn);
        *(float4*)&Bs[bkr][bn] = b4;
        __syncthreads();
#pragma unroll
        for (int kk = 0; kk < 16; kk++) {
            float4 a = *(float4*)&As[kk][trow * 4];
            float4 b = *(float4*)&Bs[kk][tcol * 4];
            c[0][0] += a.x * b.x; c[0][1] += a.x * b.y; c[0][2] += a.x * b.z; c[0][3] += a.x * b.w;
            c[1][0] += a.y * b.x; c[1][1] += a.y * b.y; c[1][2] += a.y * b.z; c[1][3] += a.y * b.w;
            c[2][0] += a.z * b.x; c[2][1] += a.z * b.y; c[2][2] += a.z * b.z; c[2][3] += a.z * b.w;
            c[3][0] += a.w * b.x; c[3][1] += a.w * b.y; c[3][2] += a.w * b.z; c[3][3] += a.w * b.w;
        }
        __syncthreads();
    }
#pragma unroll
    for (int i = 0; i < 4; i++) {
        size_t r = (size_t)(row0 + trow * 4 + i) * 256;
#pragma unroll
        for (int j = 0; j < 4; j++) {
            int cc = col0 + tcol * 4 + j;
            out[r + cc] = c[i][j] + bk[cc];
        }
    }
}

// =============================================================================
// init: sentence_style, zero state, reset group barriers. Runs every replay.
// =============================================================================
__global__ void init_kernel(const float* __restrict__ inp_att,
                            const float* __restrict__ style_token) {
    int b = blockIdx.x, d = threadIdx.x;      // 128 x 256
    float s = 0.0f;
#pragma unroll
    for (int k = 0; k < 10; k++) s += inp_att[b * 10 + k] * style_token[k * 256 + d];
    int idx = b * 256 + d;
    g_ss[idx]   = s;
    g_hatt[idx] = 0.0f; g_h1[idx] = 0.0f; g_h2[idx] = 0.0f; g_ctx[idx] = 0.0f;
    if (b == 0 && d < NGROUP * 32) g_barctr[d] = 0u;
}

// ---------------- column-phase helpers (group of 16 blocks, 16 rows) ----------
struct Seg3 { const float* a; const float* bp; const float* c; };

template<int LA, int LB>
__device__ __forceinline__ float segld(const Seg3& s, int row, int k) {
    if (LA && k < LA) return __ldcg(s.a + row * LA + k);
    if (LB && k - LA < LB) return __ldcg(s.bp + row * LB + (k - LA));
    return __ldcg(s.c + row * 256 + (k - LA - LB));
}

// Stage X k-major: Xs[k*16 + r] (16 rows contiguous per k).
template<int K, int LA, int LB>
__device__ __forceinline__ void stageXT(float* Xs, Seg3 s, int R0, int tid) {
    constexpr int total = 16 * K;
#pragma unroll
    for (int i0 = 0; i0 < total; i0 += 1024) {
        int i = i0 + tid;
        int r = i & 15, k = i >> 4;
        Xs[i] = segld<LA, LB>(s, R0 + r, k);
    }
    __syncthreads();
}

// gates: N=512, block covers 32 cols. Threads: lane=col(32), warp=(rp2, kp16).
// Each W element loaded ONCE per block; 8-row register accumulators.
template<int K>
__device__ __forceinline__ void col_gates(float* Xs, const float* __restrict__ W,
                                          const float* __restrict__ bg,
                                          const float* h, int R0, int sub, int tid) {
    const int lane = tid & 31, w = tid >> 5;
    const int rp = w >> 4, kp = w & 15;
    const int col = sub * 32 + lane;
    constexpr int KS = K / 16;
    const float* Wp = W + (size_t)(kp * KS) * 512 + col;
    const float* Xp = Xs + (kp * KS) * 16 + rp * 8;
    float acc[8];
#pragma unroll
    for (int i = 0; i < 8; i++) acc[i] = 0.0f;
#pragma unroll 4
    for (int j = 0; j < KS; j++) {
        float wv = Wp[(size_t)j * 512];
        float4 x0 = *(const float4*)(Xp + j * 16);
        float4 x1 = *(const float4*)(Xp + j * 16 + 4);
        acc[0] += wv * x0.x; acc[1] += wv * x0.y; acc[2] += wv * x0.z; acc[3] += wv * x0.w;
        acc[4] += wv * x1.x; acc[5] += wv * x1.y; acc[6] += wv * x1.z; acc[7] += wv * x1.w;
    }
    __syncthreads();                       // all Xs reads done -> reuse as partials
    float* P = Xs;
#pragma unroll
    for (int i = 0; i < 8; i++) P[kp * 512 + (rp * 8 + i) * 32 + lane] = acc[i];
    __syncthreads();
    if (tid < 512) {
        float sacc = 0.0f;
#pragma unroll
        for (int q = 0; q < 16; q++) sacc += P[q * 512 + tid];
        const int r = tid >> 5, cl = tid & 31;
        const int ccol = sub * 32 + cl, row = R0 + r;
        float y = fsig(sacc + bg[ccol]);
        if (ccol < 256) g_rh[row * 256 + ccol] = y * __ldcg(h + row * 256 + ccol);
        else            g_u [row * 256 + ccol - 256] = y;
    }
    __syncthreads();
}

// candidate: N=256, block covers 16 cols. lane=(c16, kh2); warp=(rp2, kp16).
template<int K>
__device__ __forceinline__ void col_cand(float* Xs, const float* __restrict__ W,
                                         const float* __restrict__ bc,
                                         float* h, float* o_out, const float* xadd,
                                         int R0, int sub, int tid) {
    const int lane = tid & 31, w = tid >> 5;
    const int c = lane >> 1, kh = lane & 1;
    const int rp = w >> 4, kp = w & 15;
    const int kseg = kh + 2 * kp;          // 0..31
    const int col = sub * 16 + c;
    constexpr int KS = K / 32;
    const float* Wp = W + (size_t)(kseg * KS) * 256 + col;
    const float* Xp = Xs + (kseg * KS) * 16 + rp * 8;
    float acc[8];
#pragma unroll
    for (int i = 0; i < 8; i++) acc[i] = 0.0f;
#pragma unroll 4
    for (int j = 0; j < KS; j++) {
        float wv = Wp[(size_t)j * 256];
        float4 x0 = *(const float4*)(Xp + j * 16);
        float4 x1 = *(const float4*)(Xp + j * 16 + 4);
        acc[0] += wv * x0.x; acc[1] += wv * x0.y; acc[2] += wv * x0.z; acc[3] += wv * x0.w;
        acc[4] += wv * x1.x; acc[5] += wv * x1.y; acc[6] += wv * x1.z; acc[7] += wv * x1.w;
    }
    __syncthreads();
    float* P = Xs;
#pragma unroll
    for (int i = 0; i < 8; i++) P[kseg * 256 + (rp * 8 + i) * 16 + c] = acc[i];
    __syncthreads();
    if (tid < 256) {
        float sacc = 0.0f;
#pragma unroll
        for (int q = 0; q < 32; q++) sacc += P[q * 256 + tid];
        const int r = tid >> 4, cl = tid & 15;
        const int ccol = sub * 16 + cl, row = R0 + r;
        float cv = ftanh(sacc + bc[ccol]);
        float un = __ldcg(g_u + row * 256 + ccol);
        float ho = __ldcg(h + row * 256 + ccol);
        float hn = un * ho + (1.0f - un) * cv;
        h[row * 256 + ccol] = hn;
        if (o_out) o_out[row * 256 + ccol] = hn + __ldcg(xadd + row * 256 + ccol);
    }
    __syncthreads();
}

// out GEMM: N=400 (13 blocks of 32 cols), K=256. Same layout as gates.
__device__ __forceinline__ void col_out(float* Xs, const float* __restrict__ W,
                                        const float* __restrict__ ob,
                                        float* dout, int R0, int sub, int tid, int t) {
    const int lane = tid & 31, w = tid >> 5;
    const int rp = w >> 4, kp = w & 15;
    const int col0 = sub * 32 + lane;
    const int col = (col0 < 400) ? col0 : 399;
    const float* Wp = W + (size_t)(kp * 16) * 400 + col;
    const float* Xp = Xs + (kp * 16) * 16 + rp * 8;
    float acc[8];
#pragma unroll
    for (int i = 0; i < 8; i++) acc[i] = 0.0f;
#pragma unroll 4
    for (int j = 0; j < 16; j++) {
        float wv = Wp[(size_t)j * 400];
        float4 x0 = *(const float4*)(Xp + j * 16);
        float4 x1 = *(const float4*)(Xp + j * 16 + 4);
        acc[0] += wv * x0.x; acc[1] += wv * x0.y; acc[2] += wv * x0.z; acc[3] += wv * x0.w;
        acc[4] += wv * x1.x; acc[5] += wv * x1.y; acc[6] += wv * x1.z; acc[7] += wv * x1.w;
    }
    __syncthreads();
    float* P = Xs;
#pragma unroll
    for (int i = 0; i < 8; i++) P[kp * 512 + (rp * 8 + i) * 32 + lane] = acc[i];
    __syncthreads();
    if (tid < 512) {
        float sacc = 0.0f;
#pragma unroll
        for (int q = 0; q < 16; q++) sacc += P[q * 512 + tid];
        const int r = tid >> 5, cl = tid & 31;
        const int ccol = sub * 32 + cl;
        if (ccol < 400)
            dout[(size_t)(R0 + r) * SEQ_STRIDE_B + (size_t)t * 400 + ccol] = sacc + ob[ccol];
    }
}

// =============================================================================
// Persistent scan kernel: 128 blocks x 1024 threads, whole 250-step recurrence.
// =============================================================================
__global__ void __launch_bounds__(1024, 1)
scan_kernel(const float* __restrict__ enc, const int* __restrict__ mask,
            const float* __restrict__ vvec,
            const float* __restrict__ pre_W1, const float* __restrict__ pre_b1,
            const float* __restrict__ pre_W2, const float* __restrict__ pre_b2,
            const float* __restrict__ att_Wg, const float* __restrict__ att_bg,
            const float* __restrict__ att_Wc, const float* __restrict__ att_bc,
            const float* __restrict__ attn_Wq, const float* __restrict__ attn_bq,
            const float* __restrict__ deciW, const float* __restrict__ decib,
            const float* __restrict__ d1Wg, const float* __restrict__ d1bg,
            const float* __restrict__ d1Wc, const float* __restrict__ d1bc,
            const float* __restrict__ d2Wg, const float* __restrict__ d2bg,
            const float* __restrict__ d2Wc, const float* __restrict__ d2bc,
            const float* __restrict__ outW, const float* __restrict__ outb,
            float* __restrict__ dout) {
    __shared__ float sm[10240];                  // X staging / partials / es+red (40 KB)
    __shared__ float qs[256], vs[256], hs[256], sss[256], cs[256];
    const int b = blockIdx.x, tid = threadIdx.x;
    const int g = b >> 4, sub = b & 15, R0 = g * 16;
    unsigned* ctr = &g_barctr[g * 32];
    unsigned tgt = 0;

    if (tid < 256) { vs[tid] = vvec[tid]; sss[tid] = g_ss[b * 256 + tid]; }
    const int ml = mask[b];
    const int wid = tid >> 5, lane = tid & 31;
    float* es  = sm;
    float* red = sm + 1024;

    for (int t = 0; t < T_DEC; t++) {
        // ---------- Phase 1 (row): prenet -> g_p[b] ----------
        // x = last dense_out[:, -80:] recomputed from o2 (removes P9 barrier).
        if (t == 0) {
            if (tid < 80) sm[tid] = 0.0f;
        } else {
            if (tid < 256) sm[512 + tid] = __ldcg(g_o2 + b * 256 + tid);
            __syncthreads();
            if (tid < 640) {                  // 80 cols x 8 parts (20 full warps)
                const int c = tid >> 3, part = tid & 7;
                float acc = 0.0f;
#pragma unroll 8
                for (int k = 0; k < 32; k++)
                    acc += sm[512 + part * 32 + k] * outW[(size_t)(part * 32 + k) * 400 + 320 + c];
                acc += __shfl_xor_sync(0xffffffffu, acc, 1);
                acc += __shfl_xor_sync(0xffffffffu, acc, 2);
                acc += __shfl_xor_sync(0xffffffffu, acc, 4);
                if (part == 0) sm[c] = acc + outb[320 + c];
            }
        }
        __syncthreads();
        {   // L1: 80 -> 256 relu (4 threads/col)
            const int col = tid >> 2, part = tid & 3;
            float acc = 0.0f;
#pragma unroll
            for (int k = 0; k < 20; k++) acc += sm[part * 20 + k] * pre_W1[(size_t)(part * 20 + k) * 256 + col];
            acc += __shfl_xor_sync(0xffffffffu, acc, 1);
            acc += __shfl_xor_sync(0xffffffffu, acc, 2);
            if (part == 0) sm[128 + col] = fmaxf(acc + pre_b1[col], 0.0f);
        }
        __syncthreads();
        {   // L2: 256 -> 128 relu (8 threads/col)
            const int col = tid >> 3, part = tid & 7;
            float acc = 0.0f;
#pragma unroll 8
            for (int k = 0; k < 32; k++) acc += sm[128 + part * 32 + k] * pre_W2[(size_t)(part * 32 + k) * 128 + col];
            acc += __shfl_xor_sync(0xffffffffu, acc, 1);
            acc += __shfl_xor_sync(0xffffffffu, acc, 2);
            acc += __shfl_xor_sync(0xffffffffu, acc, 4);
            if (part == 0) g_p[b * 128 + col] = fmaxf(acc + pre_b2[col], 0.0f);
        }
        gbar(ctr, tgt);

        // ---------- Phase 2 (col): att GRU gates, K=640, X=[ctx,p,hatt] ----------
        stageXT<640, 256, 128>(sm, Seg3{g_ctx, g_p, g_hatt}, R0, tid);
        col_gates<640>(sm, att_Wg, att_bg, g_hatt, R0, sub, tid);
        gbar(ctr, tgt);

        // ---------- Phase 3 (col): att GRU cand, K=640, X=[ctx,p,rh] -> hatt ----------
        stageXT<640, 256, 128>(sm, Seg3{g_ctx, g_p, g_rh}, R0, tid);
        col_cand<640>(sm, att_Wc, att_bc, g_hatt, nullptr, nullptr, R0, sub, tid);
        gbar(ctr, tgt);

        // ---------- Phase 4 (row): q, energies, softmax, context, wper, dec_in ----------
        if (tid < 256) hs[tid] = __ldcg(g_hatt + b * 256 + tid);
        __syncthreads();
        {   // q = hs @ Wq + bq (4 threads/col)
            const int col = tid >> 2, part = tid & 3;
            float acc = 0.0f;
#pragma unroll 8
            for (int k = 0; k < 64; k++) acc += hs[part * 64 + k] * attn_Wq[(size_t)(part * 64 + k) * 256 + col];
            acc += __shfl_xor_sync(0xffffffffu, acc, 1);
            acc += __shfl_xor_sync(0xffffffffu, acc, 2);
            if (part == 0) qs[col] = acc + attn_bq[col];
        }
        __syncthreads();
        {   // energies: 32 warps, 2 rows per iter for MLP=16
            float vf[8], qf[8];
#pragma unroll
            for (int j = 0; j < 8; j++) { vf[j] = vs[lane + 32 * j]; qf[j] = qs[lane + 32 * j]; }
            const float* kb2 = g_keys + (size_t)b * T_ENC * 256;
            for (int base = 0; base < 1024; base += 64) {
                const int t0 = base + wid, t1 = base + 32 + wid;
                const float* kp0 = kb2 + (size_t)t0 * 256;
                const float* kp1 = kb2 + (size_t)t1 * 256;
                float a0 = 0.0f, a1 = 0.0f;
#pragma unroll
                for (int j = 0; j < 8; j++) {
                    float x0 = __ldcs(kp0 + lane + 32 * j) + qf[j];
                    float x1 = __ldcs(kp1 + lane + 32 * j) + qf[j];
                    a0 += tanhap(x0) * vf[j];
                    a1 += tanhap(x1) * vf[j];
                }
#pragma unroll
                for (int o = 16; o; o >>= 1) {
                    a0 += __shfl_xor_sync(0xffffffffu, a0, o);
                    a1 += __shfl_xor_sync(0xffffffffu, a1, o);
                }
                if (lane == 0) {
                    es[t0] = (t0 < ml) ? a0 : -1.0e9f;
                    es[t1] = (t1 < ml) ? a1 : -1.0e9f;
                }
            }
        }
        __syncthreads();
        // softmax over 1024
        red[tid] = es[tid]; __syncthreads();
        for (int s = 512; s; s >>= 1) { if (tid < s) red[tid] = fmaxf(red[tid], red[tid + s]); __syncthreads(); }
        float mx = red[0];
        __syncthreads();
        float e0 = __expf(es[tid] - mx);
        red[tid] = e0; __syncthreads();
        for (int s = 512; s; s >>= 1) { if (tid < s) red[tid] += red[tid + s]; __syncthreads(); }
        float inv = 1.0f / red[0];
        __syncthreads();
        float a0 = e0 * inv;
        es[tid] = a0;
        dout[ALPHA_OFF + ((size_t)t * BATCH + b) * 1024 + tid] = a0;
        __syncthreads();
        {   // context + wper
            const int gq = tid >> 8, d = tid & 255;
            const float* eb = enc + (size_t)b * T_ENC * 256;
            const int tbase = gq * 256;
            float acc = 0.0f;
            for (int tt = 0; tt < 256; tt += 8) {
#pragma unroll
                for (int u2 = 0; u2 < 8; u2++)
                    acc += es[tbase + tt + u2] * __ldcs(eb + (size_t)(tbase + tt + u2) * 256 + d);
            }
            red[tid] = acc; __syncthreads();
            float f = 0.0f;
            if (tid < 256) {
                float c = red[tid] + red[tid + 256] + red[tid + 512] + red[tid + 768];
                cs[tid] = c;
                g_ctx[b * 256 + tid] = c;
                float as = fabsf(sss[tid]);
                f = __fdividef(as, fabsf(c) + as);
            }
            __syncthreads();
            red[tid] = f; __syncthreads();
            for (int s = 512; s; s >>= 1) { if (tid < s) red[tid] += red[tid + s]; __syncthreads(); }
            if (tid == 0) g_wpart[t * BATCH + b] = red[0];
            __syncthreads();
        }
        {   // dec_in = [hs, cs+sss] @ deciW + decib (4 threads/col)
            const int col = tid >> 2, part = tid & 3;
            const int kb3 = part * 128;
            float acc = 0.0f;
#pragma unroll 16
            for (int k = 0; k < 128; k++) {
                int kk = kb3 + k;
                float x = (kk < 256) ? hs[kk] : (cs[kk - 256] + sss[kk - 256]);
                acc += x * deciW[(size_t)kk * 256 + col];
            }
            acc += __shfl_xor_sync(0xffffffffu, acc, 1);
            acc += __shfl_xor_sync(0xffffffffu, acc, 2);
            if (part == 0) g_din[b * 256 + col] = acc + decib[col];
        }
        gbar(ctr, tgt);

        // ---------- Phase 5/6: dec1 GRU ----------
        stageXT<512, 256, 256>(sm, Seg3{g_din, g_h1, nullptr}, R0, tid);
        col_gates<512>(sm, d1Wg, d1bg, g_h1, R0, sub, tid);
        gbar(ctr, tgt);
        stageXT<512, 256, 256>(sm, Seg3{g_din, g_rh, nullptr}, R0, tid);
        col_cand<512>(sm, d1Wc, d1bc, g_h1, g_o1, g_din, R0, sub, tid);
        gbar(ctr, tgt);

        // ---------- Phase 7/8: dec2 GRU ----------
        stageXT<512, 256, 256>(sm, Seg3{g_o1, g_h2, nullptr}, R0, tid);
        col_gates<512>(sm, d2Wg, d2bg, g_h2, R0, sub, tid);
        gbar(ctr, tgt);
        stageXT<512, 256, 256>(sm, Seg3{g_o1, g_rh, nullptr}, R0, tid);
        col_cand<512>(sm, d2Wc, d2bc, g_h2, g_o2, g_o1, R0, sub, tid);
        gbar(ctr, tgt);

        // ---------- Phase 9 (col, no trailing barrier): dense_out -> slab ----------
        if (sub < 13) {
            stageXT<256, 256, 0>(sm, Seg3{g_o2, nullptr, nullptr}, R0, tid);
            col_out(sm, outW, outb, dout, R0, sub, tid, t);
        }
        // Safe: next-step P1 only reads g_o2; next write to g_o2 (P8 of t+1)
        // is separated from this phase by >= 6 group barriers.
    }
}

// =============================================================================
// Finalize weight_pers: deterministic reduction of 128 partials per step.
// =============================================================================
__global__ void final_kernel(float* __restrict__ dout) {
    __shared__ float red[128];
    const int t = blockIdx.x, tid = threadIdx.x;   // 250 x 128
    red[tid] = g_wpart[t * BATCH + tid];
    __syncthreads();
    for (int s = 64; s; s >>= 1) { if (tid < s) red[tid] += red[tid + s]; __syncthreads(); }
    if (tid == 0) dout[WPER_OFF + t] = red[0] * (1.0f / 32768.0f);
}

// =============================================================================
// Host
// =============================================================================
extern "C" void kernel_launch(void* const* d_in, const int* in_sizes, int n_in,
                              void* d_out, int out_size) {
    const float* enc         = (const float*)d_in[0];
    const int*   inp_mask    = (const int*)  d_in[1];
    const float* inp_att     = (const float*)d_in[2];
    const float* style_token = (const float*)d_in[3];
    const float* pre_W1 = (const float*)d_in[4];
    const float* pre_b1 = (const float*)d_in[5];
    const float* pre_W2 = (const float*)d_in[6];
    const float* pre_b2 = (const float*)d_in[7];
    const float* att_Wg = (const float*)d_in[8];
    const float* att_bg = (const float*)d_in[9];
    const float* att_Wc = (const float*)d_in[10];
    const float* att_bc = (const float*)d_in[11];
    const float* attn_Wk = (const float*)d_in[12];
    const float* attn_bk = (const float*)d_in[13];
    const float* attn_Wq = (const float*)d_in[14];
    const float* attn_bq = (const float*)d_in[15];
    const float* attn_v  = (const float*)d_in[16];
    const float* deci_W  = (const float*)d_in[17];
    const float* deci_b  = (const float*)d_in[18];
    const float* dec1_Wg = (const float*)d_in[19];
    const float* dec1_bg = (const float*)d_in[20];
    const float* dec1_Wc = (const float*)d_in[21];
    const float* dec1_bc = (const float*)d_in[22];
    const float* dec2_Wg = (const float*)d_in[23];
    const float* dec2_bg = (const float*)d_in[24];
    const float* dec2_Wc = (const float*)d_in[25];
    const float* dec2_bc = (const float*)d_in[26];
    const float* out_W   = (const float*)d_in[27];
    const float* out_b   = (const float*)d_in[28];
    float* dout = (float*)d_out;

    float* keys;
    cudaGetSymbolAddress((void**)&keys, g_keys);

    keys_gemm<<<dim3(4, (BATCH * T_ENC) / 64), 256>>>(enc, attn_Wk, attn_bk, keys);
    init_kernel<<<BATCH, 256>>>(inp_att, style_token);
    scan_kernel<<<BATCH, 1024>>>(enc, inp_mask, attn_v,
                                 pre_W1, pre_b1, pre_W2, pre_b2,
                                 att_Wg, att_bg, att_Wc, att_bc,
                                 attn_Wq, attn_bq, deci_W, deci_b,
                                 dec1_Wg, dec1_bg, dec1_Wc, dec1_bc,
                                 dec2_Wg, dec2_bg, dec2_Wc, dec2_bc,
                                 out_W, out_b, dout);
    final_kernel<<<T_DEC, 128>>>(dout);
}

// round 10
// speedup vs baseline: 1.8084x; 1.1743x over previous
#include <cuda_runtime.h>
#include <math.h>
#include <stdint.h>

// Problem constants
#define BATCH 128
#define T_ENC 1024
#define T_DEC 250
#define GS 16          // blocks per group
#define NGROUP 8
// Output layout: seq2seq (128,1250,80) | alphas (250,128,1024) | weight_pers (250)
#define SEQ_STRIDE_B 100000
#define ALPHA_OFF   12800000ll
#define WPER_OFF    45568000ll

// ---------------- device scratch ----------------
__device__ float g_keys[BATCH * T_ENC * 256];     // enc @ Wk + bk (134 MB)
__device__ float g_ss  [BATCH * 256];
__device__ float g_hatt[BATCH * 256];
__device__ float g_h1  [BATCH * 256];
__device__ float g_h2  [BATCH * 256];
__device__ float g_ctx [BATCH * 256];
__device__ float g_p   [BATCH * 128];
__device__ float g_rh  [BATCH * 256];
__device__ float g_u   [BATCH * 256];
__device__ float g_q   [BATCH * 256];
__device__ float g_din [BATCH * 256];
__device__ float g_o1  [BATCH * 256];
__device__ float g_o2  [BATCH * 256];
__device__ float g_wpart[T_DEC * BATCH];
__device__ unsigned g_barctr[NGROUP * 32];        // one ctr per group, 128B apart

// ---------------- math helpers ----------------
__device__ __forceinline__ float fsig(float x) {
    return __fdividef(1.0f, 1.0f + __expf(-x));
}
__device__ __forceinline__ float ftanh(float x) {       // accurate (GRU recurrence)
    float xx = fminf(fmaxf(x, -15.0f), 15.0f);
    float e  = __expf(2.0f * xx);
    return __fdividef(e - 1.0f, e + 1.0f);
}
__device__ __forceinline__ float tanhap(float x) {      // HW tanh (energies only)
    float y;
    asm("tanh.approx.f32 %0, %1;" : "=f"(y) : "f"(x));
    return y;
}
__device__ __forceinline__ void pfl(const float* p) {   // L2 prefetch hint
    asm volatile("prefetch.global.L2 [%0];" :: "l"(p));
}
// prefetch a column slice of W (rows x ldn), one 128B line per row at colbase
__device__ __forceinline__ void pfW(const float* W, int rows, int ldn, int colbase, int tid) {
    for (int r = tid; r < rows; r += 1024) pfl(W + (size_t)r * ldn + colbase);
}

// ---------------- group barrier (monotonic; counters reset by init each replay) --
__device__ __forceinline__ void gbar(unsigned* ctr, unsigned& tgt) {
    __syncthreads();
    tgt += GS;
    if (threadIdx.x == 0) {
        __threadfence();
        atomicAdd(ctr, 1u);
        while (*((volatile unsigned*)ctr) < tgt) { }
        __threadfence();
    }
    __syncthreads();
}

// =============================================================================
// keys = enc @ Wk + bk.  M=131072, K=256, N=256.
// =============================================================================
__global__ void keys_gemm(const float* __restrict__ A, const float* __restrict__ Wk,
                          const float* __restrict__ bk, float* __restrict__ out) {
    __shared__ float As[16][68];
    __shared__ float Bs[16][68];
    const int tid  = threadIdx.x;
    const int trow = tid >> 4, tcol = tid & 15;
    const int row0 = blockIdx.y * 64, col0 = blockIdx.x * 64;
    float c[4][4];
#pragma unroll
    for (int i = 0; i < 4; i++)
#pragma unroll
        for (int j = 0; j < 4; j++) c[i][j] = 0.0f;
    const int ar = tid >> 2, ak = (tid & 3) * 4;
    const int bkr = tid >> 4, bn = (tid & 15) * 4;
    for (int k0 = 0; k0 < 256; k0 += 16) {
        float4 a4 = *(const float4*)(A + (size_t)(row0 + ar) * 256 + k0 + ak);
        As[ak + 0][ar] = a4.x; As[ak + 1][ar] = a4.y;
        As[ak + 2][ar] = a4.z; As[ak + 3][ar] = a4.w;
        float4 b4 = *(const float4*)(Wk + (size_t)(k0 + bkr) * 256 + col0 + bn);
        *(float4*)&Bs[bkr][bn] = b4;
        __syncthreads();
#pragma unroll
        for (int kk = 0; kk < 16; kk++) {
            float4 a = *(float4*)&As[kk][trow * 4];
            float4 b = *(float4*)&Bs[kk][tcol * 4];
            c[0][0] += a.x * b.x; c[0][1] += a.x * b.y; c[0][2] += a.x * b.z; c[0][3] += a.x * b.w;
            c[1][0] += a.y * b.x; c[1][1] += a.y * b.y; c[1][2] += a.y * b.z; c[1][3] += a.y * b.w;
            c[2][0] += a.z * b.x; c[2][1] += a.z * b.y; c[2][2] += a.z * b.z; c[2][3] += a.z * b.w;
            c[3][0] += a.w * b.x; c[3][1] += a.w * b.y; c[3][2] += a.w * b.z; c[3][3] += a.w * b.w;
        }
        __syncthreads();
    }
#pragma unroll
    for (int i = 0; i < 4; i++) {
        size_t r = (size_t)(row0 + trow * 4 + i) * 256;
#pragma unroll
        for (int j = 0; j < 4; j++) {
            int cc = col0 + tcol * 4 + j;
            __stcs(out + r + cc, c[i][j] + bk[cc]);
        }
    }
}

// =============================================================================
// init: sentence_style, zero state, reset group barriers. Runs every replay.
// =============================================================================
__global__ void init_kernel(const float* __restrict__ inp_att,
                            const float* __restrict__ style_token) {
    int b = blockIdx.x, d = threadIdx.x;      // 128 x 256
    float s = 0.0f;
#pragma unroll
    for (int k = 0; k < 10; k++) s += inp_att[b * 10 + k] * style_token[k * 256 + d];
    int idx = b * 256 + d;
    g_ss[idx]   = s;
    g_hatt[idx] = 0.0f; g_h1[idx] = 0.0f; g_h2[idx] = 0.0f; g_ctx[idx] = 0.0f;
    if (b == 0 && d < NGROUP * 32) g_barctr[d] = 0u;
}

// ---------------- column-phase helpers (group of 16 blocks, 16 rows) ----------
struct Seg3 { const float* a; const float* bp; const float* c; };

template<int LA, int LB>
__device__ __forceinline__ float segld(const Seg3& s, int row, int k) {
    if (LA && k < LA) return __ldcg(s.a + row * LA + k);
    if (LB && k - LA < LB) return __ldcg(s.bp + row * LB + (k - LA));
    return __ldcg(s.c + row * 256 + (k - LA - LB));
}

// Stage X k-major: Xs[k*16 + r] (16 rows contiguous per k).
template<int K, int LA, int LB>
__device__ __forceinline__ void stageXT(float* Xs, Seg3 s, int R0, int tid) {
    constexpr int total = 16 * K;
#pragma unroll
    for (int i0 = 0; i0 < total; i0 += 1024) {
        int i = i0 + tid;
        int r = i & 15, k = i >> 4;
        Xs[i] = segld<LA, LB>(s, R0 + r, k);
    }
    __syncthreads();
}

// Stage for dec_in: X = [hatt | ctx + ss], K=512.
__device__ __forceinline__ void stageDin(float* Xs, int R0, int tid) {
#pragma unroll
    for (int i0 = 0; i0 < 16 * 512; i0 += 1024) {
        int i = i0 + tid;
        int r = i & 15, k = i >> 4;
        int row = R0 + r;
        float v;
        if (k < 256) v = __ldcg(g_hatt + row * 256 + k);
        else {
            int k2 = k - 256;
            v = __ldcg(g_ctx + row * 256 + k2) + __ldcg(g_ss + row * 256 + k2);
        }
        Xs[i] = v;
    }
    __syncthreads();
}

// gates: N=512, block covers 32 cols. lane=col(32), warp=(rp2, kp16).
template<int K>
__device__ __forceinline__ void col_gates(float* Xs, const float* __restrict__ W,
                                          const float* __restrict__ bg,
                                          const float* h, int R0, int sub, int tid) {
    const int lane = tid & 31, w = tid >> 5;
    const int rp = w >> 4, kp = w & 15;
    const int col = sub * 32 + lane;
    constexpr int KS = K / 16;
    const float* Wp = W + (size_t)(kp * KS) * 512 + col;
    const float* Xp = Xs + (kp * KS) * 16 + rp * 8;
    float acc[8];
#pragma unroll
    for (int i = 0; i < 8; i++) acc[i] = 0.0f;
#pragma unroll 8
    for (int j = 0; j < KS; j++) {
        float wv = Wp[(size_t)j * 512];
        float4 x0 = *(const float4*)(Xp + j * 16);
        float4 x1 = *(const float4*)(Xp + j * 16 + 4);
        acc[0] += wv * x0.x; acc[1] += wv * x0.y; acc[2] += wv * x0.z; acc[3] += wv * x0.w;
        acc[4] += wv * x1.x; acc[5] += wv * x1.y; acc[6] += wv * x1.z; acc[7] += wv * x1.w;
    }
    __syncthreads();
    float* P = Xs;
#pragma unroll
    for (int i = 0; i < 8; i++) P[kp * 512 + (rp * 8 + i) * 32 + lane] = acc[i];
    __syncthreads();
    if (tid < 512) {
        float sacc = 0.0f;
#pragma unroll
        for (int q = 0; q < 16; q++) sacc += P[q * 512 + tid];
        const int r = tid >> 5, cl = tid & 31;
        const int ccol = sub * 32 + cl, row = R0 + r;
        float y = fsig(sacc + bg[ccol]);
        if (ccol < 256) g_rh[row * 256 + ccol] = y * __ldcg(h + row * 256 + ccol);
        else            g_u [row * 256 + ccol - 256] = y;
    }
    __syncthreads();
}

// candidate: N=256, block covers 16 cols. lane=(c16, kh2); warp=(rp2, kp16).
template<int K>
__device__ __forceinline__ void col_cand(float* Xs, const float* __restrict__ W,
                                         const float* __restrict__ bc,
                                         float* h, float* o_out, const float* xadd,
                                         int R0, int sub, int tid) {
    const int lane = tid & 31, w = tid >> 5;
    const int c = lane >> 1, kh = lane & 1;
    const int rp = w >> 4, kp = w & 15;
    const int kseg = kh + 2 * kp;          // 0..31
    const int col = sub * 16 + c;
    constexpr int KS = K / 32;
    const float* Wp = W + (size_t)(kseg * KS) * 256 + col;
    const float* Xp = Xs + (kseg * KS) * 16 + rp * 8;
    float acc[8];
#pragma unroll
    for (int i = 0; i < 8; i++) acc[i] = 0.0f;
#pragma unroll 8
    for (int j = 0; j < KS; j++) {
        float wv = Wp[(size_t)j * 256];
        float4 x0 = *(const float4*)(Xp + j * 16);
        float4 x1 = *(const float4*)(Xp + j * 16 + 4);
        acc[0] += wv * x0.x; acc[1] += wv * x0.y; acc[2] += wv * x0.z; acc[3] += wv * x0.w;
        acc[4] += wv * x1.x; acc[5] += wv * x1.y; acc[6] += wv * x1.z; acc[7] += wv * x1.w;
    }
    __syncthreads();
    float* P = Xs;
#pragma unroll
    for (int i = 0; i < 8; i++) P[kseg * 256 + (rp * 8 + i) * 16 + c] = acc[i];
    __syncthreads();
    if (tid < 256) {
        float sacc = 0.0f;
#pragma unroll
        for (int q = 0; q < 32; q++) sacc += P[q * 256 + tid];
        const int r = tid >> 4, cl = tid & 15;
        const int ccol = sub * 16 + cl, row = R0 + r;
        float cv = ftanh(sacc + bc[ccol]);
        float un = __ldcg(g_u + row * 256 + ccol);
        float ho = __ldcg(h + row * 256 + ccol);
        float hn = un * ho + (1.0f - un) * cv;
        h[row * 256 + ccol] = hn;
        if (o_out) o_out[row * 256 + ccol] = hn + __ldcg(xadd + row * 256 + ccol);
    }
    __syncthreads();
}

// plain N=256 GEMM (q, dec_in): same layout as col_cand, linear epilogue.
template<int K>
__device__ __forceinline__ void col_plain(float* Xs, const float* __restrict__ W,
                                          const float* __restrict__ bias,
                                          float* out, int R0, int sub, int tid) {
    const int lane = tid & 31, w = tid >> 5;
    const int c = lane >> 1, kh = lane & 1;
    const int rp = w >> 4, kp = w & 15;
    const int kseg = kh + 2 * kp;
    const int col = sub * 16 + c;
    constexpr int KS = K / 32;
    const float* Wp = W + (size_t)(kseg * KS) * 256 + col;
    const float* Xp = Xs + (kseg * KS) * 16 + rp * 8;
    float acc[8];
#pragma unroll
    for (int i = 0; i < 8; i++) acc[i] = 0.0f;
#pragma unroll 8
    for (int j = 0; j < KS; j++) {
        float wv = Wp[(size_t)j * 256];
        float4 x0 = *(const float4*)(Xp + j * 16);
        float4 x1 = *(const float4*)(Xp + j * 16 + 4);
        acc[0] += wv * x0.x; acc[1] += wv * x0.y; acc[2] += wv * x0.z; acc[3] += wv * x0.w;
        acc[4] += wv * x1.x; acc[5] += wv * x1.y; acc[6] += wv * x1.z; acc[7] += wv * x1.w;
    }
    __syncthreads();
    float* P = Xs;
#pragma unroll
    for (int i = 0; i < 8; i++) P[kseg * 256 + (rp * 8 + i) * 16 + c] = acc[i];
    __syncthreads();
    if (tid < 256) {
        float sacc = 0.0f;
#pragma unroll
        for (int q = 0; q < 32; q++) sacc += P[q * 256 + tid];
        const int r = tid >> 4, cl = tid & 15;
        const int ccol = sub * 16 + cl;
        out[(R0 + r) * 256 + ccol] = sacc + bias[ccol];
    }
    __syncthreads();
}

// out GEMM: N=400 (13 blocks of 32 cols), K=256.
__device__ __forceinline__ void col_out(float* Xs, const float* __restrict__ W,
                                        const float* __restrict__ ob,
                                        float* dout, int R0, int sub, int tid, int t) {
    const int lane = tid & 31, w = tid >> 5;
    const int rp = w >> 4, kp = w & 15;
    const int col0 = sub * 32 + lane;
    const int col = (col0 < 400) ? col0 : 399;
    const float* Wp = W + (size_t)(kp * 16) * 400 + col;
    const float* Xp = Xs + (kp * 16) * 16 + rp * 8;
    float acc[8];
#pragma unroll
    for (int i = 0; i < 8; i++) acc[i] = 0.0f;
#pragma unroll 8
    for (int j = 0; j < 16; j++) {
        float wv = Wp[(size_t)j * 400];
        float4 x0 = *(const float4*)(Xp + j * 16);
        float4 x1 = *(const float4*)(Xp + j * 16 + 4);
        acc[0] += wv * x0.x; acc[1] += wv * x0.y; acc[2] += wv * x0.z; acc[3] += wv * x0.w;
        acc[4] += wv * x1.x; acc[5] += wv * x1.y; acc[6] += wv * x1.z; acc[7] += wv * x1.w;
    }
    __syncthreads();
    float* P = Xs;
#pragma unroll
    for (int i = 0; i < 8; i++) P[kp * 512 + (rp * 8 + i) * 32 + lane] = acc[i];
    __syncthreads();
    if (tid < 512) {
        float sacc = 0.0f;
#pragma unroll
        for (int q = 0; q < 16; q++) sacc += P[q * 512 + tid];
        const int r = tid >> 5, cl = tid & 31;
        const int ccol = sub * 32 + cl;
        if (ccol < 400)
            __stcs(dout + (size_t)(R0 + r) * SEQ_STRIDE_B + (size_t)t * 400 + ccol, sacc + ob[ccol]);
    }
}

// =============================================================================
// Persistent scan kernel: 128 blocks x 1024 threads, whole 250-step recurrence.
// =============================================================================
__global__ void __launch_bounds__(1024, 1)
scan_kernel(const float* __restrict__ enc, const int* __restrict__ mask,
            const float* __restrict__ vvec,
            const float* __restrict__ pre_W1, const float* __restrict__ pre_b1,
            const float* __restrict__ pre_W2, const float* __restrict__ pre_b2,
            const float* __restrict__ att_Wg, const float* __restrict__ att_bg,
            const float* __restrict__ att_Wc, const float* __restrict__ att_bc,
            const float* __restrict__ attn_Wq, const float* __restrict__ attn_bq,
            const float* __restrict__ deciW, const float* __restrict__ decib,
            const float* __restrict__ d1Wg, const float* __restrict__ d1bg,
            const float* __restrict__ d1Wc, const float* __restrict__ d1bc,
            const float* __restrict__ d2Wg, const float* __restrict__ d2bg,
            const float* __restrict__ d2Wc, const float* __restrict__ d2bc,
            const float* __restrict__ outW, const float* __restrict__ outb,
            float* __restrict__ dout) {
    __shared__ float sm[10240];                  // X staging / partials / es+red (40 KB)
    __shared__ float qs[256], vs[256], sss[256];
    const int b = blockIdx.x, tid = threadIdx.x;
    const int g = b >> 4, sub = b & 15, R0 = g * 16;
    unsigned* ctr = &g_barctr[g * 32];
    unsigned tgt = 0;

    if (tid < 256) { vs[tid] = vvec[tid]; sss[tid] = g_ss[b * 256 + tid]; }
    const int ml = mask[b];
    const int wid = tid >> 5, lane = tid & 31;
    float* es  = sm;
    float* red = sm + 1024;

    for (int t = 0; t < T_DEC; t++) {
        // ---------- P1 (row): prenet -> g_p[b] ----------
        if (t == 0) {
            if (tid < 80) sm[tid] = 0.0f;
        } else {
            if (tid < 256) sm[512 + tid] = __ldcg(g_o2 + b * 256 + tid);
            __syncthreads();
            if (tid < 640) {                  // 80 cols x 8 parts
                const int c = tid >> 3, part = tid & 7;
                float acc = 0.0f;
#pragma unroll 8
                for (int k = 0; k < 32; k++)
                    acc += sm[512 + part * 32 + k] * outW[(size_t)(part * 32 + k) * 400 + 320 + c];
                acc += __shfl_xor_sync(0xffffffffu, acc, 1);
                acc += __shfl_xor_sync(0xffffffffu, acc, 2);
                acc += __shfl_xor_sync(0xffffffffu, acc, 4);
                if (part == 0) sm[c] = acc + outb[320 + c];
            }
        }
        __syncthreads();
        {   // L1: 80 -> 256 relu
            const int col = tid >> 2, part = tid & 3;
            float acc = 0.0f;
#pragma unroll
            for (int k = 0; k < 20; k++) acc += sm[part * 20 + k] * pre_W1[(size_t)(part * 20 + k) * 256 + col];
            acc += __shfl_xor_sync(0xffffffffu, acc, 1);
            acc += __shfl_xor_sync(0xffffffffu, acc, 2);
            if (part == 0) sm[128 + col] = fmaxf(acc + pre_b1[col], 0.0f);
        }
        __syncthreads();
        {   // L2: 256 -> 128 relu
            const int col = tid >> 3, part = tid & 7;
            float acc = 0.0f;
#pragma unroll 8
            for (int k = 0; k < 32; k++) acc += sm[128 + part * 32 + k] * pre_W2[(size_t)(part * 32 + k) * 128 + col];
            acc += __shfl_xor_sync(0xffffffffu, acc, 1);
            acc += __shfl_xor_sync(0xffffffffu, acc, 2);
            acc += __shfl_xor_sync(0xffffffffu, acc, 4);
            if (part == 0) g_p[b * 128 + col] = fmaxf(acc + pre_b2[col], 0.0f);
        }
        pfW(att_Wg, 640, 512, sub * 32, tid);
        gbar(ctr, tgt);                                           // B1

        // ---------- P2 (col): att GRU gates, K=640 ----------
        stageXT<640, 256, 128>(sm, Seg3{g_ctx, g_p, g_hatt}, R0, tid);
        col_gates<640>(sm, att_Wg, att_bg, g_hatt, R0, sub, tid);
        pfW(att_Wc, 640, 256, sub * 16, tid);
        gbar(ctr, tgt);                                           // B2

        // ---------- P3 (col): att GRU cand -> hatt ----------
        stageXT<640, 256, 128>(sm, Seg3{g_ctx, g_p, g_rh}, R0, tid);
        col_cand<640>(sm, att_Wc, att_bc, g_hatt, nullptr, nullptr, R0, sub, tid);
        pfW(attn_Wq, 256, 256, sub * 16, tid);
        gbar(ctr, tgt);                                           // B3

        // ---------- P3q (col): q = hatt @ Wq + bq ----------
        stageXT<256, 256, 0>(sm, Seg3{g_hatt, nullptr, nullptr}, R0, tid);
        col_plain<256>(sm, attn_Wq, attn_bq, g_q, R0, sub, tid);
        pfW(deciW, 512, 256, sub * 16, tid);
        gbar(ctr, tgt);                                           // B4

        // ---------- P4 (row): energies, softmax, alpha, context, wper ----------
        if (tid < 256) qs[tid] = __ldcg(g_q + b * 256 + tid);
        es[tid] = -1.0e9f;
        __syncthreads();
        {   // energies: 32 warps, 2 rows/iter (MLP 16); only t < ml
            float vf[8], qf[8];
#pragma unroll
            for (int j = 0; j < 8; j++) { vf[j] = vs[lane + 32 * j]; qf[j] = qs[lane + 32 * j]; }
            const float* kb2 = g_keys + (size_t)b * T_ENC * 256;
            for (int base = 0; base < ml; base += 64) {
                const int t0 = base + wid, t1 = base + 32 + wid;
                const float* kp0 = kb2 + (size_t)t0 * 256;
                const float* kp1 = kb2 + (size_t)t1 * 256;
                float a0 = 0.0f, a1 = 0.0f;
#pragma unroll
                for (int j = 0; j < 8; j++) {
                    float x0 = __ldcs(kp0 + lane + 32 * j) + qf[j];
                    float x1 = __ldcs(kp1 + lane + 32 * j) + qf[j];
                    a0 += tanhap(x0) * vf[j];
                    a1 += tanhap(x1) * vf[j];
                }
#pragma unroll
                for (int o = 16; o; o >>= 1) {
                    a0 += __shfl_xor_sync(0xffffffffu, a0, o);
                    a1 += __shfl_xor_sync(0xffffffffu, a1, o);
                }
                if (lane == 0) {
                    es[t0] = (t0 < ml) ? a0 : -1.0e9f;
                    es[t1] = (t1 < ml) ? a1 : -1.0e9f;
                }
            }
        }
        __syncthreads();
        // softmax (two-level shuffle reductions)
        float m = es[tid];
#pragma unroll
        for (int o = 16; o; o >>= 1) m = fmaxf(m, __shfl_xor_sync(0xffffffffu, m, o));
        if (lane == 0) red[wid] = m;
        __syncthreads();
        if (tid < 32) {
            float m2 = red[tid];
#pragma unroll
            for (int o = 16; o; o >>= 1) m2 = fmaxf(m2, __shfl_xor_sync(0xffffffffu, m2, o));
            if (tid == 0) red[32] = m2;
        }
        __syncthreads();
        const float mx = red[32];
        float e0 = __expf(es[tid] - mx);
        float esum = e0;
#pragma unroll
        for (int o = 16; o; o >>= 1) esum += __shfl_xor_sync(0xffffffffu, esum, o);
        if (lane == 0) red[wid] = esum;
        __syncthreads();
        if (tid < 32) {
            float s2 = red[tid];
#pragma unroll
            for (int o = 16; o; o >>= 1) s2 += __shfl_xor_sync(0xffffffffu, s2, o);
            if (tid == 0) red[33] = s2;
        }
        __syncthreads();
        const float inv = __fdividef(1.0f, red[33]);
        float a0 = e0 * inv;
        es[tid] = a0;
        __stcs(dout + ALPHA_OFF + ((size_t)t * BATCH + b) * 1024 + tid, a0);
        __syncthreads();
        {   // context (only t < ml) + wper
            const int gq = tid >> 8, d = tid & 255;
            const float* eb = enc + (size_t)b * T_ENC * 256;
            const int tbase = gq << 8;
            float acc = 0.0f;
            const int rem = ml - tbase;
            if (rem > 0) {
                const int cnt = (rem >= 256) ? 256 : ((rem + 15) & ~15);
                for (int tt = 0; tt < cnt; tt += 16) {
#pragma unroll
                    for (int u2 = 0; u2 < 16; u2++)
                        acc += es[tbase + tt + u2] * __ldcs(eb + (size_t)(tbase + tt + u2) * 256 + d);
                }
            }
            red[tid] = acc;
            __syncthreads();
            float f = 0.0f;
            if (tid < 256) {
                float c = red[tid] + red[tid + 256] + red[tid + 512] + red[tid + 768];
                g_ctx[b * 256 + tid] = c;
                float as = fabsf(sss[tid]);
                f = __fdividef(as, fabsf(c) + as);
            }
            __syncthreads();
#pragma unroll
            for (int o = 16; o; o >>= 1) f += __shfl_xor_sync(0xffffffffu, f, o);
            if (lane == 0) red[wid] = f;
            __syncthreads();
            if (tid < 32) {
                float f2 = red[tid];
#pragma unroll
                for (int o = 16; o; o >>= 1) f2 += __shfl_xor_sync(0xffffffffu, f2, o);
                if (tid == 0) g_wpart[t * BATCH + b] = f2;
            }
        }
        pfW(d1Wg, 512, 512, sub * 32, tid);
        gbar(ctr, tgt);                                           // B5

        // ---------- P4d (col): dec_in = [hatt, ctx+ss] @ deciW ----------
        stageDin(sm, R0, tid);
        col_plain<512>(sm, deciW, decib, g_din, R0, sub, tid);
        pfW(d1Wc, 512, 256, sub * 16, tid);
        gbar(ctr, tgt);                                           // B6

        // ---------- P5/P6: dec1 GRU ----------
        stageXT<512, 256, 256>(sm, Seg3{g_din, g_h1, nullptr}, R0, tid);
        col_gates<512>(sm, d1Wg, d1bg, g_h1, R0, sub, tid);
        pfW(d2Wg, 512, 512, sub * 32, tid);
        gbar(ctr, tgt);                                           // B7
        stageXT<512, 256, 256>(sm, Seg3{g_din, g_rh, nullptr}, R0, tid);
        col_cand<512>(sm, d1Wc, d1bc, g_h1, g_o1, g_din, R0, sub, tid);
        pfW(d2Wc, 512, 256, sub * 16, tid);
        gbar(ctr, tgt);                                           // B8

        // ---------- P7/P8: dec2 GRU ----------
        stageXT<512, 256, 256>(sm, Seg3{g_o1, g_h2, nullptr}, R0, tid);
        col_gates<512>(sm, d2Wg, d2bg, g_h2, R0, sub, tid);
        if (sub < 13) pfW(outW, 256, 400, sub * 32, tid);
        gbar(ctr, tgt);                                           // B9
        stageXT<512, 256, 256>(sm, Seg3{g_o1, g_rh, nullptr}, R0, tid);
        col_cand<512>(sm, d2Wc, d2bc, g_h2, g_o2, g_o1, R0, sub, tid);
        // prefetch next-step P1 weights during the barrier + P9
        for (int i = tid * 32; i < 80 * 256; i += 1024 * 32) pfl(pre_W1 + i);
        for (int i = tid * 32; i < 256 * 128; i += 1024 * 32) pfl(pre_W2 + i);
        if (tid < 256) {
            pfl(outW + (size_t)tid * 400 + 320);
            pfl(outW + (size_t)tid * 400 + 352);
            pfl(outW + (size_t)tid * 400 + 384);
        }
        gbar(ctr, tgt);                                           // B10

        // ---------- P9 (col, no trailing barrier): dense_out -> slab ----------
        if (sub < 13) {
            stageXT<256, 256, 0>(sm, Seg3{g_o2, nullptr, nullptr}, R0, tid);
            col_out(sm, outW, outb, dout, R0, sub, tid, t);
        }
        // Safe: next-step P1 reads only g_o2 (covered by B10); next write of
        // g_o2 is P8 of t+1, many barriers away.
    }
}

// =============================================================================
// Finalize weight_pers: deterministic reduction of 128 partials per step.
// =============================================================================
__global__ void final_kernel(float* __restrict__ dout) {
    __shared__ float red[128];
    const int t = blockIdx.x, tid = threadIdx.x;   // 250 x 128
    red[tid] = g_wpart[t * BATCH + tid];
    __syncthreads();
    for (int s = 64; s; s >>= 1) { if (tid < s) red[tid] += red[tid + s]; __syncthreads(); }
    if (tid == 0) dout[WPER_OFF + t] = red[0] * (1.0f / 32768.0f);
}

// =============================================================================
// Host
// =============================================================================
extern "C" void kernel_launch(void* const* d_in, const int* in_sizes, int n_in,
                              void* d_out, int out_size) {
    const float* enc         = (const float*)d_in[0];
    const int*   inp_mask    = (const int*)  d_in[1];
    const float* inp_att     = (const float*)d_in[2];
    const float* style_token = (const float*)d_in[3];
    const float* pre_W1 = (const float*)d_in[4];
    const float* pre_b1 = (const float*)d_in[5];
    const float* pre_W2 = (const float*)d_in[6];
    const float* pre_b2 = (const float*)d_in[7];
    const float* att_Wg = (const float*)d_in[8];
    const float* att_bg = (const float*)d_in[9];
    const float* att_Wc = (const float*)d_in[10];
    const float* att_bc = (const float*)d_in[11];
    const float* attn_Wk = (const float*)d_in[12];
    const float* attn_bk = (const float*)d_in[13];
    const float* attn_Wq = (const float*)d_in[14];
    const float* attn_bq = (const float*)d_in[15];
    const float* attn_v  = (const float*)d_in[16];
    const float* deci_W  = (const float*)d_in[17];
    const float* deci_b  = (const float*)d_in[18];
    const float* dec1_Wg = (const float*)d_in[19];
    const float* dec1_bg = (const float*)d_in[20];
    const float* dec1_Wc = (const float*)d_in[21];
    const float* dec1_bc = (const float*)d_in[22];
    const float* dec2_Wg = (const float*)d_in[23];
    const float* dec2_bg = (const float*)d_in[24];
    const float* dec2_Wc = (const float*)d_in[25];
    const float* dec2_bc = (const float*)d_in[26];
    const float* out_W   = (const float*)d_in[27];
    const float* out_b   = (const float*)d_in[28];
    float* dout = (float*)d_out;

    float* keys;
    cudaGetSymbolAddress((void**)&keys, g_keys);

    keys_gemm<<<dim3(4, (BATCH * T_ENC) / 64), 256>>>(enc, attn_Wk, attn_bk, keys);
    init_kernel<<<BATCH, 256>>>(inp_att, style_token);
    scan_kernel<<<BATCH, 1024>>>(enc, inp_mask, attn_v,
                                 pre_W1, pre_b1, pre_W2, pre_b2,
                                 att_Wg, att_bg, att_Wc, att_bc,
                                 attn_Wq, attn_bq, deci_W, deci_b,
                                 dec1_Wg, dec1_bg, dec1_Wc, dec1_bc,
                                 dec2_Wg, dec2_bg, dec2_Wc, dec2_bc,
                                 out_W, out_b, dout);
    final_kernel<<<T_DEC, 128>>>(dout);
}